// round 13
// baseline (speedup 1.0000x reference)
#include <cuda_runtime.h>
#include <cuda_fp16.h>
#include <cstdint>

// Problem constants (B=4,S=2048,I=4096,O=4096,G=128)
#define M_DIM 8192
#define N_DIM 4096
#define K_DIM 4096

#define BM 128
#define BN 128
#define BK 64
#define STAGES 2
#define NKT (K_DIM / BK)              // 64
#define A_BYTES (BM * 128)            // 16384
#define B_BYTES (BN * 128)            // 16384
#define STAGE_BYTES (A_BYTES + B_BYTES)          // 32768
#define SMEM_TOTAL (STAGES * STAGE_BYTES)        // 65536 (x3 CTAs = 192KB/SM)

// Device-global scratch (no allocation allowed)
__device__ __half g_xh[(size_t)M_DIM * K_DIM];     // 64 MB fp16 x
__device__ __half g_wdeq[(size_t)N_DIM * K_DIM];   // 32 MB fp16 dequant W

// ------- Kernel 1: fused convert (x f32->f16) + dequant (w*s f32->f16) ------
#define XBLK ((M_DIM * (K_DIM / 8)) / 256)   // 16384
#define WBLK ((N_DIM * (K_DIM / 8)) / 256)   // 8192

__global__ void prep_kernel(const float* __restrict__ x,
                            const float* __restrict__ w,
                            const float* __restrict__ s) {
    int blk = blockIdx.x;
    if (blk < XBLK) {
        size_t base = ((size_t)blk * blockDim.x + threadIdx.x) << 3;
        float4 v0 = *reinterpret_cast<const float4*>(x + base);
        float4 v1 = *reinterpret_cast<const float4*>(x + base + 4);
        __half2 h[4];
        h[0] = __floats2half2_rn(v0.x, v0.y);
        h[1] = __floats2half2_rn(v0.z, v0.w);
        h[2] = __floats2half2_rn(v1.x, v1.y);
        h[3] = __floats2half2_rn(v1.z, v1.w);
        *reinterpret_cast<uint4*>(g_xh + base) = *reinterpret_cast<uint4*>(h);
    } else {
        size_t base = ((size_t)(blk - XBLK) * blockDim.x + threadIdx.x) << 3;
        int o = (int)(base >> 12);
        int k = (int)(base & (K_DIM - 1));
        float sc = s[(o << 5) + (k >> 7)];
        float4 v0 = *reinterpret_cast<const float4*>(w + base);
        float4 v1 = *reinterpret_cast<const float4*>(w + base + 4);
        __half2 h[4];
        h[0] = __floats2half2_rn(v0.x * sc, v0.y * sc);
        h[1] = __floats2half2_rn(v0.z * sc, v0.w * sc);
        h[2] = __floats2half2_rn(v1.x * sc, v1.y * sc);
        h[3] = __floats2half2_rn(v1.z * sc, v1.w * sc);
        *reinterpret_cast<uint4*>(g_wdeq + base) = *reinterpret_cast<uint4*>(h);
    }
}

// ---------------- helpers ----------------------------------------------------
__device__ __forceinline__ void cp16(uint32_t dst, const void* src) {
    asm volatile("cp.async.cg.shared.global [%0], [%1], 16;\n" :: "r"(dst), "l"(src));
}
__device__ __forceinline__ void cp_commit() {
    asm volatile("cp.async.commit_group;\n");
}
template <int N>
__device__ __forceinline__ void cp_wait() {
    asm volatile("cp.async.wait_group %0;\n" :: "n"(N));
}
__device__ __forceinline__ void ldm_x4(uint32_t* r, uint32_t addr) {
    asm volatile("ldmatrix.sync.aligned.m8n8.x4.shared.b16 {%0,%1,%2,%3}, [%4];\n"
                 : "=r"(r[0]), "=r"(r[1]), "=r"(r[2]), "=r"(r[3])
                 : "r"(addr));
}
__device__ __forceinline__ void mma16816(float* c, const uint32_t* a,
                                         uint32_t b0, uint32_t b1) {
    asm volatile(
        "mma.sync.aligned.m16n8k16.row.col.f32.f16.f16.f32 "
        "{%0,%1,%2,%3}, {%4,%5,%6,%7}, {%8,%9}, {%0,%1,%2,%3};\n"
        : "+f"(c[0]), "+f"(c[1]), "+f"(c[2]), "+f"(c[3])
        : "r"(a[0]), "r"(a[1]), "r"(a[2]), "r"(a[3]), "r"(b0), "r"(b1));
}

// Smem tiles: 128B rows, 8 x 16B chunks, XOR swizzle phys = chunk ^ (row & 7).
// Stage: A (128 rows) at +0, B (128 rows) at +A_BYTES.
// 128 threads: ldRow = tid>>3 (0..15), 8 row-iters of 16.
__device__ __forceinline__ void load_stage(uint32_t tiles, int slot, int kt,
                                           const __half* Abase, const __half* Bbase,
                                           int ldRow, int ldChunk) {
    uint32_t sA = tiles + slot * STAGE_BYTES;
    uint32_t sB = sA + A_BYTES;
    int koff = kt * BK;
#pragma unroll
    for (int i = 0; i < 8; i++) {
        int row = ldRow + i * 16;
        uint32_t sw = (uint32_t)(row * 128 + ((ldChunk ^ (row & 7)) * 16));
        cp16(sA + sw, Abase + (size_t)row * K_DIM + koff);
        cp16(sB + sw, Bbase + (size_t)row * K_DIM + koff);
    }
}

// ---------------- Kernel 2: fp16 GEMM + bias --------------------------------
extern __shared__ char smem_raw[];

__global__ void __launch_bounds__(128, 3)
gemm_kernel(const float* __restrict__ bias, float* __restrict__ out) {
    const int tid = threadIdx.x;
    const int lane = tid & 31;
    const int warp = tid >> 5;      // 0..3
    const int warp_m = warp >> 1;   // 0..1 -> 64 rows
    const int warp_n = warp & 1;    // 0..1 -> 64 cols
    const int m0 = blockIdx.y * BM;
    const int n0 = blockIdx.x * BN;

    uint32_t tiles;
    asm("{ .reg .u64 t; cvta.to.shared.u64 t, %1; cvt.u32.u64 %0, t; }"
        : "=r"(tiles) : "l"(smem_raw));

    const int ldRow = tid >> 3;     // 0..15
    const int ldChunk = tid & 7;    // 0..7
    const __half* Abase = g_xh + (size_t)m0 * K_DIM + ldChunk * 8;
    const __half* Bbase = g_wdeq + (size_t)n0 * K_DIM + ldChunk * 8;

    float acc[4][8][4];
#pragma unroll
    for (int i = 0; i < 4; i++)
#pragma unroll
        for (int j = 0; j < 8; j++)
#pragma unroll
            for (int k = 0; k < 4; k++) acc[i][j][k] = 0.0f;

    // ldmatrix lane addressing
    const int a_r = lane & 15;
    const int a_cs = lane >> 4;
    const int b_r = (lane & 7) + ((lane >> 4) << 3);
    const int b_cs = (lane >> 3) & 1;

    // prologue: stage 0
    load_stage(tiles, 0, 0, Abase, Bbase, ldRow, ldChunk);
    cp_commit();

    for (int kt = 0; kt < NKT; kt++) {
        cp_wait<0>();               // tile kt resident (own part)
        __syncthreads();            // everyone's part; prev compute done

        if (kt + 1 < NKT)
            load_stage(tiles, (kt + 1) & 1, kt + 1, Abase, Bbase, ldRow, ldChunk);
        cp_commit();

        uint32_t sA = tiles + (kt & 1) * STAGE_BYTES;
        uint32_t sB = sA + A_BYTES;
#pragma unroll
        for (int ks = 0; ks < 4; ks++) {
            uint32_t a[4][4];
#pragma unroll
            for (int mt = 0; mt < 4; mt++) {
                int row = warp_m * 64 + mt * 16 + a_r;
                int chunk = ks * 2 + a_cs;
                ldm_x4(a[mt], sA + row * 128 + ((chunk ^ (row & 7)) * 16));
            }
            uint32_t b[4][4];
#pragma unroll
            for (int nt2 = 0; nt2 < 4; nt2++) {
                int row = warp_n * 64 + nt2 * 16 + b_r;
                int chunk = ks * 2 + b_cs;
                ldm_x4(b[nt2], sB + row * 128 + ((chunk ^ (row & 7)) * 16));
            }
#pragma unroll
            for (int mt = 0; mt < 4; mt++)
#pragma unroll
                for (int nt = 0; nt < 8; nt++)
                    mma16816(acc[mt][nt], a[mt],
                             b[nt >> 1][(nt & 1) * 2],
                             b[nt >> 1][(nt & 1) * 2 + 1]);
        }
    }

    // epilogue: + bias, round through fp16 (match reference grid), f32 out
    const int r = lane >> 2;
    const int c2 = (lane & 3) * 2;
#pragma unroll
    for (int nt = 0; nt < 8; nt++) {
        int n = n0 + warp_n * 64 + nt * 8 + c2;
        float b0f = bias[n];
        float b1f = bias[n + 1];
#pragma unroll
        for (int mt = 0; mt < 4; mt++) {
            int m = m0 + warp_m * 64 + mt * 16 + r;
            float2 v0, v1;
            v0.x = __half2float(__float2half_rn(acc[mt][nt][0] + b0f));
            v0.y = __half2float(__float2half_rn(acc[mt][nt][1] + b1f));
            v1.x = __half2float(__float2half_rn(acc[mt][nt][2] + b0f));
            v1.y = __half2float(__float2half_rn(acc[mt][nt][3] + b1f));
            *reinterpret_cast<float2*>(out + (size_t)m * N_DIM + n) = v0;
            *reinterpret_cast<float2*>(out + (size_t)(m + 8) * N_DIM + n) = v1;
        }
    }
}

// ---------------- Launch -----------------------------------------------------
extern "C" void kernel_launch(void* const* d_in, const int* in_sizes, int n_in,
                              void* d_out, int out_size) {
    const float* x      = (const float*)d_in[0];
    const float* weight = (const float*)d_in[1];
    const float* scales = (const float*)d_in[2];
    const float* bias   = (const float*)d_in[3];
    float* out = (float*)d_out;

    prep_kernel<<<XBLK + WBLK, 256>>>(x, weight, scales);

    cudaFuncSetAttribute(gemm_kernel,
                         cudaFuncAttributeMaxDynamicSharedMemorySize,
                         SMEM_TOTAL);
    dim3 grid(N_DIM / BN, M_DIM / BM);   // (32, 64) = 2048 CTAs
    gemm_kernel<<<grid, 128, SMEM_TOTAL>>>(bias, out);
}

// round 16
// speedup vs baseline: 1.0696x; 1.0696x over previous
#include <cuda_runtime.h>
#include <cuda_fp16.h>
#include <cstdint>

// Problem constants (B=4,S=2048,I=4096,O=4096,G=128)
#define M_DIM 8192
#define N_DIM 4096
#define K_DIM 4096

#define BM 128
#define BN 128
#define BK 64
#define STAGES 3
#define NKT (K_DIM / BK)              // 64
#define A_BYTES (BM * 128)            // 16384
#define B_BYTES (BN * 128)            // 16384
#define STAGE_BYTES (A_BYTES + B_BYTES)          // 32768
#define SMEM_TOTAL (STAGES * STAGE_BYTES)        // 98304 (x2 CTAs = 192KB/SM)

// Device-global scratch (no allocation allowed)
__device__ __half g_xh[(size_t)M_DIM * K_DIM];     // 64 MB fp16 x
__device__ __half g_wdeq[(size_t)N_DIM * K_DIM];   // 32 MB fp16 dequant W

// ------- Kernel 1: fused convert (x f32->f16) + dequant (w*s f32->f16) ------
#define XBLK ((M_DIM * (K_DIM / 8)) / 256)   // 16384
#define WBLK ((N_DIM * (K_DIM / 8)) / 256)   // 8192

__global__ void prep_kernel(const float* __restrict__ x,
                            const float* __restrict__ w,
                            const float* __restrict__ s) {
    int blk = blockIdx.x;
    if (blk < XBLK) {
        size_t base = ((size_t)blk * blockDim.x + threadIdx.x) << 3;
        float4 v0 = *reinterpret_cast<const float4*>(x + base);
        float4 v1 = *reinterpret_cast<const float4*>(x + base + 4);
        __half2 h[4];
        h[0] = __floats2half2_rn(v0.x, v0.y);
        h[1] = __floats2half2_rn(v0.z, v0.w);
        h[2] = __floats2half2_rn(v1.x, v1.y);
        h[3] = __floats2half2_rn(v1.z, v1.w);
        *reinterpret_cast<uint4*>(g_xh + base) = *reinterpret_cast<uint4*>(h);
    } else {
        size_t base = ((size_t)(blk - XBLK) * blockDim.x + threadIdx.x) << 3;
        int o = (int)(base >> 12);
        int k = (int)(base & (K_DIM - 1));
        float sc = s[(o << 5) + (k >> 7)];
        float4 v0 = *reinterpret_cast<const float4*>(w + base);
        float4 v1 = *reinterpret_cast<const float4*>(w + base + 4);
        __half2 h[4];
        h[0] = __floats2half2_rn(v0.x * sc, v0.y * sc);
        h[1] = __floats2half2_rn(v0.z * sc, v0.w * sc);
        h[2] = __floats2half2_rn(v1.x * sc, v1.y * sc);
        h[3] = __floats2half2_rn(v1.z * sc, v1.w * sc);
        *reinterpret_cast<uint4*>(g_wdeq + base) = *reinterpret_cast<uint4*>(h);
    }
}

// ---------------- helpers ----------------------------------------------------
__device__ __forceinline__ void cp16(uint32_t dst, const void* src) {
    asm volatile("cp.async.cg.shared.global [%0], [%1], 16;\n" :: "r"(dst), "l"(src));
}
__device__ __forceinline__ void cp_commit() {
    asm volatile("cp.async.commit_group;\n");
}
template <int N>
__device__ __forceinline__ void cp_wait() {
    asm volatile("cp.async.wait_group %0;\n" :: "n"(N));
}
__device__ __forceinline__ void ldm_x4(uint32_t* r, uint32_t addr) {
    asm volatile("ldmatrix.sync.aligned.m8n8.x4.shared.b16 {%0,%1,%2,%3}, [%4];\n"
                 : "=r"(r[0]), "=r"(r[1]), "=r"(r[2]), "=r"(r[3])
                 : "r"(addr));
}
__device__ __forceinline__ void mma16816(float* c, const uint32_t* a,
                                         uint32_t b0, uint32_t b1) {
    asm volatile(
        "mma.sync.aligned.m16n8k16.row.col.f32.f16.f16.f32 "
        "{%0,%1,%2,%3}, {%4,%5,%6,%7}, {%8,%9}, {%0,%1,%2,%3};\n"
        : "+f"(c[0]), "+f"(c[1]), "+f"(c[2]), "+f"(c[3])
        : "r"(a[0]), "r"(a[1]), "r"(a[2]), "r"(a[3]), "r"(b0), "r"(b1));
}

// Smem tiles: 128B rows, 8 x 16B chunks, XOR swizzle phys = chunk ^ (row & 7).
// Stage: A (128 rows) at +0, B (128 rows) at +A_BYTES.
// 128 threads: ldRow = tid>>3 (0..15), 8 row-iters of 16.
__device__ __forceinline__ void load_stage(uint32_t tiles, int slot, int kt,
                                           const __half* Abase, const __half* Bbase,
                                           int ldRow, int ldChunk) {
    uint32_t sA = tiles + slot * STAGE_BYTES;
    uint32_t sB = sA + A_BYTES;
    int koff = kt * BK;
#pragma unroll
    for (int i = 0; i < 8; i++) {
        int row = ldRow + i * 16;
        uint32_t sw = (uint32_t)(row * 128 + ((ldChunk ^ (row & 7)) * 16));
        cp16(sA + sw, Abase + (size_t)row * K_DIM + koff);
        cp16(sB + sw, Bbase + (size_t)row * K_DIM + koff);
    }
}

// ---------------- Kernel 2: fp16 GEMM + bias --------------------------------
extern __shared__ char smem_raw[];

__global__ void __launch_bounds__(128, 2)
gemm_kernel(const float* __restrict__ bias, float* __restrict__ out) {
    const int tid = threadIdx.x;
    const int lane = tid & 31;
    const int warp = tid >> 5;      // 0..3
    const int warp_m = warp >> 1;   // 0..1 -> 64 rows
    const int warp_n = warp & 1;    // 0..1 -> 64 cols
    const int m0 = blockIdx.y * BM;
    const int n0 = blockIdx.x * BN;

    uint32_t tiles;
    asm("{ .reg .u64 t; cvta.to.shared.u64 t, %1; cvt.u32.u64 %0, t; }"
        : "=r"(tiles) : "l"(smem_raw));

    const int ldRow = tid >> 3;     // 0..15
    const int ldChunk = tid & 7;    // 0..7
    const __half* Abase = g_xh + (size_t)m0 * K_DIM + ldChunk * 8;
    const __half* Bbase = g_wdeq + (size_t)n0 * K_DIM + ldChunk * 8;

    float acc[4][8][4];
#pragma unroll
    for (int i = 0; i < 4; i++)
#pragma unroll
        for (int j = 0; j < 8; j++)
#pragma unroll
            for (int k = 0; k < 4; k++) acc[i][j][k] = 0.0f;

    // ldmatrix lane addressing
    const int a_r = lane & 15;
    const int a_cs = lane >> 4;
    const int b_r = (lane & 7) + ((lane >> 4) << 3);
    const int b_cs = (lane >> 3) & 1;
    const int a_row0 = warp_m * 64 + a_r;
    const int b_row0 = warp_n * 64 + b_r;

    // prologue: fill STAGES-1 stages
#pragma unroll
    for (int s = 0; s < STAGES - 1; s++) {
        load_stage(tiles, s, s, Abase, Bbase, ldRow, ldChunk);
        cp_commit();
    }

    uint32_t a[4][4];        // single-buffered A fragments
    uint32_t b[2][4][4];     // double-buffered B fragments

    for (int kt = 0; kt < NKT; kt++) {
        cp_wait<STAGES - 2>();      // tile kt resident
        __syncthreads();

        int nxt = kt + STAGES - 1;
        if (nxt < NKT)
            load_stage(tiles, nxt % STAGES, nxt, Abase, Bbase, ldRow, ldChunk);
        cp_commit();

        uint32_t sA = tiles + (kt % STAGES) * STAGE_BYTES;
        uint32_t sB = sA + A_BYTES;

        // preload ks=0 fragments
#pragma unroll
        for (int mt = 0; mt < 4; mt++) {
            int row = a_row0 + mt * 16;
            int chunk = a_cs;
            ldm_x4(a[mt], sA + row * 128 + ((chunk ^ (row & 7)) * 16));
        }
#pragma unroll
        for (int nt2 = 0; nt2 < 4; nt2++) {
            int row = b_row0 + nt2 * 16;
            int chunk = b_cs;
            ldm_x4(b[0][nt2], sB + row * 128 + ((chunk ^ (row & 7)) * 16));
        }

#pragma unroll
        for (int ks = 0; ks < 4; ks++) {
            const int cur = ks & 1;
            // hide B latency: issue next-ks B loads before this ks' MMAs
            if (ks < 3) {
#pragma unroll
                for (int nt2 = 0; nt2 < 4; nt2++) {
                    int row = b_row0 + nt2 * 16;
                    int chunk = (ks + 1) * 2 + b_cs;
                    ldm_x4(b[cur ^ 1][nt2],
                           sB + row * 128 + ((chunk ^ (row & 7)) * 16));
                }
            }
#pragma unroll
            for (int mt = 0; mt < 4; mt++)
#pragma unroll
                for (int nt = 0; nt < 8; nt++)
                    mma16816(acc[mt][nt], a[mt],
                             b[cur][nt >> 1][(nt & 1) * 2],
                             b[cur][nt >> 1][(nt & 1) * 2 + 1]);
            // reload A for next ks (after its last use above)
            if (ks < 3) {
#pragma unroll
                for (int mt = 0; mt < 4; mt++) {
                    int row = a_row0 + mt * 16;
                    int chunk = (ks + 1) * 2 + a_cs;
                    ldm_x4(a[mt], sA + row * 128 + ((chunk ^ (row & 7)) * 16));
                }
            }
        }
    }

    // epilogue: + bias, round through fp16 (match reference grid), f32 out
    const int r = lane >> 2;
    const int c2 = (lane & 3) * 2;
#pragma unroll
    for (int nt = 0; nt < 8; nt++) {
        int n = n0 + warp_n * 64 + nt * 8 + c2;
        float b0f = bias[n];
        float b1f = bias[n + 1];
#pragma unroll
        for (int mt = 0; mt < 4; mt++) {
            int m = m0 + warp_m * 64 + mt * 16 + r;
            float2 v0, v1;
            v0.x = __half2float(__float2half_rn(acc[mt][nt][0] + b0f));
            v0.y = __half2float(__float2half_rn(acc[mt][nt][1] + b1f));
            v1.x = __half2float(__float2half_rn(acc[mt][nt][2] + b0f));
            v1.y = __half2float(__float2half_rn(acc[mt][nt][3] + b1f));
            *reinterpret_cast<float2*>(out + (size_t)m * N_DIM + n) = v0;
            *reinterpret_cast<float2*>(out + (size_t)(m + 8) * N_DIM + n) = v1;
        }
    }
}

// ---------------- Launch -----------------------------------------------------
extern "C" void kernel_launch(void* const* d_in, const int* in_sizes, int n_in,
                              void* d_out, int out_size) {
    const float* x      = (const float*)d_in[0];
    const float* weight = (const float*)d_in[1];
    const float* scales = (const float*)d_in[2];
    const float* bias   = (const float*)d_in[3];
    float* out = (float*)d_out;

    prep_kernel<<<XBLK + WBLK, 256>>>(x, weight, scales);

    cudaFuncSetAttribute(gemm_kernel,
                         cudaFuncAttributeMaxDynamicSharedMemorySize,
                         SMEM_TOTAL);
    dim3 grid(N_DIM / BN, M_DIM / BM);   // (32, 64) = 2048 CTAs
    gemm_kernel<<<grid, 128, SMEM_TOTAL>>>(bias, out);
}

// round 17
// speedup vs baseline: 1.1261x; 1.0529x over previous
#include <cuda_runtime.h>
#include <cuda_fp16.h>
#include <cstdint>

// Problem constants (B=4,S=2048,I=4096,O=4096,G=128)
#define M_DIM 8192
#define N_DIM 4096
#define K_DIM 4096

#define BM 128
#define BN 128
#define BK 64
#define STAGES 3
#define NKT (K_DIM / BK)              // 64
#define A_BYTES (BM * 128)            // 16384
#define B_BYTES (BN * 128)            // 16384
#define STAGE_BYTES (A_BYTES + B_BYTES)          // 32768
#define SMEM_TOTAL (STAGES * STAGE_BYTES)        // 98304 (x2 CTAs = 192KB/SM)

// Device-global scratch (no allocation allowed)
__device__ __half g_xh[(size_t)M_DIM * K_DIM];     // 64 MB fp16 x
__device__ __half g_wdeq[(size_t)N_DIM * K_DIM];   // 32 MB fp16 dequant W

// ------- Kernel 1: fused convert (x f32->f16) + dequant (w*s f32->f16) ------
#define XBLK ((M_DIM * (K_DIM / 8)) / 256)   // 16384
#define WBLK ((N_DIM * (K_DIM / 8)) / 256)   // 8192

__global__ void prep_kernel(const float* __restrict__ x,
                            const float* __restrict__ w,
                            const float* __restrict__ s) {
    int blk = blockIdx.x;
    if (blk < XBLK) {
        size_t base = ((size_t)blk * blockDim.x + threadIdx.x) << 3;
        float4 v0 = *reinterpret_cast<const float4*>(x + base);
        float4 v1 = *reinterpret_cast<const float4*>(x + base + 4);
        __half2 h[4];
        h[0] = __floats2half2_rn(v0.x, v0.y);
        h[1] = __floats2half2_rn(v0.z, v0.w);
        h[2] = __floats2half2_rn(v1.x, v1.y);
        h[3] = __floats2half2_rn(v1.z, v1.w);
        *reinterpret_cast<uint4*>(g_xh + base) = *reinterpret_cast<uint4*>(h);
    } else {
        size_t base = ((size_t)(blk - XBLK) * blockDim.x + threadIdx.x) << 3;
        int o = (int)(base >> 12);
        int k = (int)(base & (K_DIM - 1));
        float sc = s[(o << 5) + (k >> 7)];
        float4 v0 = *reinterpret_cast<const float4*>(w + base);
        float4 v1 = *reinterpret_cast<const float4*>(w + base + 4);
        __half2 h[4];
        h[0] = __floats2half2_rn(v0.x * sc, v0.y * sc);
        h[1] = __floats2half2_rn(v0.z * sc, v0.w * sc);
        h[2] = __floats2half2_rn(v1.x * sc, v1.y * sc);
        h[3] = __floats2half2_rn(v1.z * sc, v1.w * sc);
        *reinterpret_cast<uint4*>(g_wdeq + base) = *reinterpret_cast<uint4*>(h);
    }
}

// ---------------- helpers ----------------------------------------------------
__device__ __forceinline__ void cp16(uint32_t dst, const void* src) {
    asm volatile("cp.async.cg.shared.global [%0], [%1], 16;\n" :: "r"(dst), "l"(src));
}
__device__ __forceinline__ void cp_commit() {
    asm volatile("cp.async.commit_group;\n");
}
template <int N>
__device__ __forceinline__ void cp_wait() {
    asm volatile("cp.async.wait_group %0;\n" :: "n"(N));
}
__device__ __forceinline__ void ldm_x4(uint32_t* r, uint32_t addr) {
    asm volatile("ldmatrix.sync.aligned.m8n8.x4.shared.b16 {%0,%1,%2,%3}, [%4];\n"
                 : "=r"(r[0]), "=r"(r[1]), "=r"(r[2]), "=r"(r[3])
                 : "r"(addr));
}
__device__ __forceinline__ void mma16816(float* c, const uint32_t* a,
                                         uint32_t b0, uint32_t b1) {
    asm volatile(
        "mma.sync.aligned.m16n8k16.row.col.f32.f16.f16.f32 "
        "{%0,%1,%2,%3}, {%4,%5,%6,%7}, {%8,%9}, {%0,%1,%2,%3};\n"
        : "+f"(c[0]), "+f"(c[1]), "+f"(c[2]), "+f"(c[3])
        : "r"(a[0]), "r"(a[1]), "r"(a[2]), "r"(a[3]), "r"(b0), "r"(b1));
}

// Smem tiles: 128B rows, 8 x 16B chunks, XOR swizzle phys = chunk ^ (row & 7).
// Stage: A (128 rows) at +0, B (128 rows) at +A_BYTES.
// 128 threads: ldRow = tid>>3 (0..15), 8 row-iters of 16.
__device__ __forceinline__ void load_stage(uint32_t tiles, int slot, int kt,
                                           const __half* Abase, const __half* Bbase,
                                           int ldRow, int ldChunk) {
    uint32_t sA = tiles + slot * STAGE_BYTES;
    uint32_t sB = sA + A_BYTES;
    int koff = kt * BK;
#pragma unroll
    for (int i = 0; i < 8; i++) {
        int row = ldRow + i * 16;
        uint32_t sw = (uint32_t)(row * 128 + ((ldChunk ^ (row & 7)) * 16));
        cp16(sA + sw, Abase + (size_t)row * K_DIM + koff);
        cp16(sB + sw, Bbase + (size_t)row * K_DIM + koff);
    }
}

// ---------------- Kernel 2: fp16 GEMM + bias --------------------------------
extern __shared__ char smem_raw[];

__global__ void __launch_bounds__(128, 2)
gemm_kernel(const float* __restrict__ bias, float* __restrict__ out) {
    const int tid = threadIdx.x;
    const int lane = tid & 31;
    const int warp = tid >> 5;      // 0..3
    const int warp_m = warp >> 1;   // 0..1 -> 64 rows
    const int warp_n = warp & 1;    // 0..1 -> 64 cols
    const int m0 = blockIdx.y * BM;
    const int n0 = blockIdx.x * BN;

    uint32_t tiles;
    asm("{ .reg .u64 t; cvta.to.shared.u64 t, %1; cvt.u32.u64 %0, t; }"
        : "=r"(tiles) : "l"(smem_raw));

    const int ldRow = tid >> 3;     // 0..15
    const int ldChunk = tid & 7;    // 0..7
    const __half* Abase = g_xh + (size_t)m0 * K_DIM + ldChunk * 8;
    const __half* Bbase = g_wdeq + (size_t)n0 * K_DIM + ldChunk * 8;

    float acc[4][8][4];
#pragma unroll
    for (int i = 0; i < 4; i++)
#pragma unroll
        for (int j = 0; j < 8; j++)
#pragma unroll
            for (int k = 0; k < 4; k++) acc[i][j][k] = 0.0f;

    // ldmatrix lane addressing
    const int a_r = lane & 15;
    const int a_cs = lane >> 4;
    const int b_r = (lane & 7) + ((lane >> 4) << 3);
    const int b_cs = (lane >> 3) & 1;
    const int a_row0 = warp_m * 64 + a_r;
    const int b_row0 = warp_n * 64 + b_r;

    // prologue: load tiles 0 and 1, make them visible to ALL warps
    load_stage(tiles, 0, 0, Abase, Bbase, ldRow, ldChunk);
    cp_commit();
    load_stage(tiles, 1, 1, Abase, Bbase, ldRow, ldChunk);
    cp_commit();
    cp_wait<0>();
    __syncthreads();

    uint32_t a[2][4][4];     // double-buffered A fragments
    uint32_t b[2][4][4];     // double-buffered B fragments

    // preload (kt=0, ks=0) into buffer 0
#pragma unroll
    for (int mt = 0; mt < 4; mt++) {
        int row = a_row0 + mt * 16;
        int chunk = a_cs;
        ldm_x4(a[0][mt], tiles + row * 128 + ((chunk ^ (row & 7)) * 16));
    }
#pragma unroll
    for (int nt2 = 0; nt2 < 4; nt2++) {
        int row = b_row0 + nt2 * 16;
        int chunk = b_cs;
        ldm_x4(b[0][nt2], tiles + A_BYTES + row * 128 + ((chunk ^ (row & 7)) * 16));
    }

    for (int kt = 0; kt < NKT; kt++) {
        // refill slot (kt+2)%3 (last read at iter kt-1; ordered by end-of-iter sync)
        int nxt = kt + 2;
        if (nxt < NKT)
            load_stage(tiles, nxt % STAGES, nxt, Abase, Bbase, ldRow, ldChunk);
        cp_commit();

        uint32_t sA = tiles + (kt % STAGES) * STAGE_BYTES;
        uint32_t sB = sA + A_BYTES;
        uint32_t sA1 = tiles + ((kt + 1) % STAGES) * STAGE_BYTES;
        uint32_t sB1 = sA1 + A_BYTES;

#pragma unroll
        for (int ks = 0; ks < 4; ks++) {
            const int cur = ks & 1;
            const int nb = cur ^ 1;
            // prefetch next fragments (same tile, or tile kt+1 ks=0) before MMAs
            if (ks < 3) {
#pragma unroll
                for (int mt = 0; mt < 4; mt++) {
                    int row = a_row0 + mt * 16;
                    int chunk = (ks + 1) * 2 + a_cs;
                    ldm_x4(a[nb][mt], sA + row * 128 + ((chunk ^ (row & 7)) * 16));
                }
#pragma unroll
                for (int nt2 = 0; nt2 < 4; nt2++) {
                    int row = b_row0 + nt2 * 16;
                    int chunk = (ks + 1) * 2 + b_cs;
                    ldm_x4(b[nb][nt2], sB + row * 128 + ((chunk ^ (row & 7)) * 16));
                }
            } else if (kt + 1 < NKT) {
#pragma unroll
                for (int mt = 0; mt < 4; mt++) {
                    int row = a_row0 + mt * 16;
                    int chunk = a_cs;
                    ldm_x4(a[nb][mt], sA1 + row * 128 + ((chunk ^ (row & 7)) * 16));
                }
#pragma unroll
                for (int nt2 = 0; nt2 < 4; nt2++) {
                    int row = b_row0 + nt2 * 16;
                    int chunk = b_cs;
                    ldm_x4(b[nb][nt2], sB1 + row * 128 + ((chunk ^ (row & 7)) * 16));
                }
            }
#pragma unroll
            for (int mt = 0; mt < 4; mt++)
#pragma unroll
                for (int nt = 0; nt < 8; nt++)
                    mma16816(acc[mt][nt], a[cur][mt],
                             b[cur][nt >> 1][(nt & 1) * 2],
                             b[cur][nt >> 1][(nt & 1) * 2 + 1]);
        }

        // end-of-iter: own groups (incl. kt+2) complete, then block-wide visibility.
        // Establishes: tiles kt+1, kt+2 resident for all warps at next iter top.
        cp_wait<0>();
        __syncthreads();
    }

    // epilogue: + bias, round through fp16 (match reference grid), f32 out
    const int r = lane >> 2;
    const int c2 = (lane & 3) * 2;
#pragma unroll
    for (int nt = 0; nt < 8; nt++) {
        int n = n0 + warp_n * 64 + nt * 8 + c2;
        float b0f = bias[n];
        float b1f = bias[n + 1];
#pragma unroll
        for (int mt = 0; mt < 4; mt++) {
            int m = m0 + warp_m * 64 + mt * 16 + r;
            float2 v0, v1;
            v0.x = __half2float(__float2half_rn(acc[mt][nt][0] + b0f));
            v0.y = __half2float(__float2half_rn(acc[mt][nt][1] + b1f));
            v1.x = __half2float(__float2half_rn(acc[mt][nt][2] + b0f));
            v1.y = __half2float(__float2half_rn(acc[mt][nt][3] + b1f));
            *reinterpret_cast<float2*>(out + (size_t)m * N_DIM + n) = v0;
            *reinterpret_cast<float2*>(out + (size_t)(m + 8) * N_DIM + n) = v1;
        }
    }
}

// ---------------- Launch -----------------------------------------------------
extern "C" void kernel_launch(void* const* d_in, const int* in_sizes, int n_in,
                              void* d_out, int out_size) {
    const float* x      = (const float*)d_in[0];
    const float* weight = (const float*)d_in[1];
    const float* scales = (const float*)d_in[2];
    const float* bias   = (const float*)d_in[3];
    float* out = (float*)d_out;

    prep_kernel<<<XBLK + WBLK, 256>>>(x, weight, scales);

    cudaFuncSetAttribute(gemm_kernel,
                         cudaFuncAttributeMaxDynamicSharedMemorySize,
                         SMEM_TOTAL);
    dim3 grid(N_DIM / BN, M_DIM / BM);   // (32, 64) = 2048 CTAs
    gemm_kernel<<<grid, 128, SMEM_TOTAL>>>(bias, out);
}